// round 1
// baseline (speedup 1.0000x reference)
#include <cuda_runtime.h>
#include <cuda_bf16.h>
#include <math.h>

// Problem: out = GELU_exact(x @ W.T + b)
//   x: [8192, 512] f32 row-major   (d_in[0])
//   adj: [8192,8192] i32 (UNUSED)  (d_in[1])
//   W: [512, 512] f32 row-major    (d_in[2])  -> C[n,o] = sum_k x[n,k]*W[o,k]
//   b: [512] f32                   (d_in[3])
//   a: [8,128] f32 (UNUSED)        (d_in[4])
//   out: [8192, 512] f32

#define NN 8192
#define KK 512
#define OO 512

#define BM 128
#define BN 128
#define BK 16
#define PAD 4
#define LDS_M (BM + PAD)   // 132 floats; 132*4=528 bytes, 16B-aligned rows

__device__ __forceinline__ float gelu_exact(float h) {
    return 0.5f * h * (1.0f + erff(h * 0.70710678118654752f));
}

__global__ __launch_bounds__(256)
void gemm_bias_gelu_kernel(const float* __restrict__ A,   // x [N,K]
                           const float* __restrict__ B,   // W [O,K]
                           const float* __restrict__ bias,
                           float* __restrict__ C) {
    __shared__ float As[2][BK][LDS_M];
    __shared__ float Bs[2][BK][LDS_M];

    const int tid = threadIdx.x;
    const int tx = tid & 15;        // 0..15 -> output cols
    const int ty = tid >> 4;        // 0..15 -> output rows

    const int n0 = blockIdx.x * BM; // row block
    const int o0 = blockIdx.y * BN; // col block

    // micro-tile: rows {ty*4+0..3, 64+ty*4+0..3}, cols {tx*4+0..3, 64+tx*4+0..3}
    const int r0 = ty * 4;
    const int r1 = ty * 4 + 64;
    const int c0 = tx * 4;
    const int c1 = tx * 4 + 64;

    float acc[8][8];
#pragma unroll
    for (int i = 0; i < 8; i++)
#pragma unroll
        for (int j = 0; j < 8; j++) acc[i][j] = 0.0f;

    // Tile loading map: 512 float4 per tile (128 rows x 4 quads); 256 threads x 2.
    // idx = tid + 256*it ; row = idx>>2 ; q = idx&3
    const int lrow0 = tid >> 2;          // 0..63
    const int lq    = tid & 3;           // quad within the 16-wide k slice
    // second load covers rows 64..127
    float4 stageA[2], stageB[2];

    // ---- load tile 0 ----
    {
        const float* Ap = A + (long)(n0 + lrow0) * KK + lq * 4;
        const float* Bp = B + (long)(o0 + lrow0) * KK + lq * 4;
        stageA[0] = *(const float4*)(Ap);
        stageA[1] = *(const float4*)(Ap + 64 * KK);
        stageB[0] = *(const float4*)(Bp);
        stageB[1] = *(const float4*)(Bp + 64 * KK);
#pragma unroll
        for (int h = 0; h < 2; h++) {
            int row = lrow0 + h * 64;
            As[0][lq * 4 + 0][row] = stageA[h].x;
            As[0][lq * 4 + 1][row] = stageA[h].y;
            As[0][lq * 4 + 2][row] = stageA[h].z;
            As[0][lq * 4 + 3][row] = stageA[h].w;
            Bs[0][lq * 4 + 0][row] = stageB[h].x;
            Bs[0][lq * 4 + 1][row] = stageB[h].y;
            Bs[0][lq * 4 + 2][row] = stageB[h].z;
            Bs[0][lq * 4 + 3][row] = stageB[h].w;
        }
    }
    __syncthreads();

    const int T = KK / BK;   // 32
    int buf = 0;

    for (int t = 0; t < T; t++) {
        // prefetch next tile into registers
        if (t < T - 1) {
            const int k0 = (t + 1) * BK;
            const float* Ap = A + (long)(n0 + lrow0) * KK + k0 + lq * 4;
            const float* Bp = B + (long)(o0 + lrow0) * KK + k0 + lq * 4;
            stageA[0] = *(const float4*)(Ap);
            stageA[1] = *(const float4*)(Ap + 64 * KK);
            stageB[0] = *(const float4*)(Bp);
            stageB[1] = *(const float4*)(Bp + 64 * KK);
        }

        // compute on current buffer
#pragma unroll
        for (int kk = 0; kk < BK; kk++) {
            float4 a0 = *(const float4*)&As[buf][kk][r0];
            float4 a1 = *(const float4*)&As[buf][kk][r1];
            float4 b0 = *(const float4*)&Bs[buf][kk][c0];
            float4 b1 = *(const float4*)&Bs[buf][kk][c1];
            float ar[8] = {a0.x, a0.y, a0.z, a0.w, a1.x, a1.y, a1.z, a1.w};
            float br[8] = {b0.x, b0.y, b0.z, b0.w, b1.x, b1.y, b1.z, b1.w};
#pragma unroll
            for (int i = 0; i < 8; i++)
#pragma unroll
                for (int j = 0; j < 8; j++)
                    acc[i][j] = fmaf(ar[i], br[j], acc[i][j]);
        }

        if (t < T - 1) {
            int nb = buf ^ 1;
#pragma unroll
            for (int h = 0; h < 2; h++) {
                int row = lrow0 + h * 64;
                As[nb][lq * 4 + 0][row] = stageA[h].x;
                As[nb][lq * 4 + 1][row] = stageA[h].y;
                As[nb][lq * 4 + 2][row] = stageA[h].z;
                As[nb][lq * 4 + 3][row] = stageA[h].w;
                Bs[nb][lq * 4 + 0][row] = stageB[h].x;
                Bs[nb][lq * 4 + 1][row] = stageB[h].y;
                Bs[nb][lq * 4 + 2][row] = stageB[h].z;
                Bs[nb][lq * 4 + 3][row] = stageB[h].w;
            }
            __syncthreads();
            buf = nb;
        }
    }

    // epilogue: bias + exact GELU, vectorized float4 stores
    float bia0[4], bia1[4];
#pragma unroll
    for (int j = 0; j < 4; j++) {
        bia0[j] = bias[o0 + c0 + j];
        bia1[j] = bias[o0 + c1 + j];
    }

#pragma unroll
    for (int i = 0; i < 8; i++) {
        int row = n0 + ((i < 4) ? (r0 + i) : (r1 + i - 4));
        float4 v0, v1;
        v0.x = gelu_exact(acc[i][0] + bia0[0]);
        v0.y = gelu_exact(acc[i][1] + bia0[1]);
        v0.z = gelu_exact(acc[i][2] + bia0[2]);
        v0.w = gelu_exact(acc[i][3] + bia0[3]);
        v1.x = gelu_exact(acc[i][4] + bia1[0]);
        v1.y = gelu_exact(acc[i][5] + bia1[1]);
        v1.z = gelu_exact(acc[i][6] + bia1[2]);
        v1.w = gelu_exact(acc[i][7] + bia1[3]);
        *(float4*)(C + (long)row * OO + o0 + c0) = v0;
        *(float4*)(C + (long)row * OO + o0 + c1) = v1;
    }
}

extern "C" void kernel_launch(void* const* d_in, const int* in_sizes, int n_in,
                              void* d_out, int out_size) {
    const float* x = (const float*)d_in[0];
    // d_in[1] = adj (unused), d_in[4] = a (unused)
    const float* W = (const float*)d_in[2];
    const float* b = (const float*)d_in[3];
    float* out = (float*)d_out;

    dim3 grid(NN / BM, OO / BN);  // (64, 4)
    gemm_bias_gelu_kernel<<<grid, 256>>>(x, W, b, out);
}

// round 4
// speedup vs baseline: 1.8520x; 1.8520x over previous
#include <cuda_runtime.h>
#include <cuda_bf16.h>
#include <cstdint>
#include <math.h>

// out = GELU_exact(x @ W.T + b)
// x:[8192,512]f32  W:[512,512]f32  b:[512]f32  out:[8192,512]f32
// Split-precision bf16 GEMM via mma.sync (HMMA): acc += Ahi*Bhi + Ahi*Blo + Alo*Bhi
// (fp32 accumulate). Pack pass converts f32 -> bf16 hi/lo once; main pass is a
// cp.async double-buffered tiled GEMM with ldmatrix + m16n8k16 bf16 mma.

#define NN 8192
#define KK 512
#define OO 512

#define BM 256
#define BN 128
#define BK 32
#define NKT (KK / BK)          // 16
#define THREADS 512

// stage layout (bytes): Ahi[256x32] 16K | Alo 16K | Bhi[128x32] 8K | Blo 8K
#define ST_ALO  16384
#define ST_BHI  32768
#define ST_BLO  40960
#define STAGE   49152
#define SMEM_TOTAL (2 * STAGE)   // 96 KB

// packed bf16 buffers (device-global scratch is the allowed mechanism)
__device__ __align__(128) __nv_bfloat16 g_xhi[NN * KK];
__device__ __align__(128) __nv_bfloat16 g_xlo[NN * KK];
__device__ __align__(128) __nv_bfloat16 g_whi[OO * KK];
__device__ __align__(128) __nv_bfloat16 g_wlo[OO * KK];

__device__ __forceinline__ uint32_t smem_u32(const void* p) {
    uint32_t a;
    asm("{ .reg .u64 t; cvta.to.shared.u64 t, %1; cvt.u32.u64 %0, t; }" : "=r"(a) : "l"(p));
    return a;
}

#define CP16(dst, src) \
    asm volatile("cp.async.cg.shared.global [%0], [%1], 16;" :: "r"(dst), "l"(src) : "memory")
#define CP_COMMIT() asm volatile("cp.async.commit_group;" ::: "memory")
#define CP_WAIT1()  asm volatile("cp.async.wait_group 1;" ::: "memory")
#define CP_WAIT0()  asm volatile("cp.async.wait_group 0;" ::: "memory")

__device__ __forceinline__ void ldm4(uint32_t* r, uint32_t addr) {
    asm volatile("ldmatrix.sync.aligned.m8n8.x4.shared.b16 {%0,%1,%2,%3}, [%4];"
                 : "=r"(r[0]), "=r"(r[1]), "=r"(r[2]), "=r"(r[3]) : "r"(addr));
}

__device__ __forceinline__ void mma_bf16(float* d, const uint32_t* a, const uint32_t* b) {
    asm volatile(
        "mma.sync.aligned.m16n8k16.row.col.f32.bf16.bf16.f32 "
        "{%0,%1,%2,%3}, {%4,%5,%6,%7}, {%8,%9}, {%0,%1,%2,%3};"
        : "+f"(d[0]), "+f"(d[1]), "+f"(d[2]), "+f"(d[3])
        : "r"(a[0]), "r"(a[1]), "r"(a[2]), "r"(a[3]), "r"(b[0]), "r"(b[1]));
}

// swizzled byte offset inside a tile: row r (64B rows = 4 x 16B chunks), chunk c
__device__ __forceinline__ uint32_t swz(int r, int c) {
    return (uint32_t)(r * 64 + ((c ^ ((r >> 1) & 3)) << 4));
}

// A&S 7.1.26 erf (abs err 1.5e-7) -> exact-form GELU well within 1e-3
__device__ __forceinline__ float gelu_f(float h) {
    float s = h * 0.70710678118654752f;
    float a = fabsf(s);
    float t = __frcp_rn(fmaf(0.3275911f, a, 1.0f));
    float p = fmaf(fmaf(fmaf(fmaf(1.061405429f, t, -1.453152027f), t, 1.421413741f),
                        t, -0.284496736f), t, 0.254829592f) * t;
    float e = __expf(-a * a);
    float erfv = fmaf(-p, e, 1.0f);
    erfv = copysignf(erfv, s);
    return 0.5f * h * (1.0f + erfv);
}

// ---------------- pack kernel: f32 -> bf16 hi/lo ----------------
__global__ __launch_bounds__(256) void pack_kernel(const float* __restrict__ x,
                                                   const float* __restrict__ W) {
    const int g = blockIdx.x * 256 + threadIdx.x;
    const int A_GROUPS = NN * (KK / 8);   // 524288
    const float* src;
    __nv_bfloat16 *dhi, *dlo;
    if (g < A_GROUPS) {
        src = x + (size_t)g * 8;
        dhi = g_xhi + (size_t)g * 8;
        dlo = g_xlo + (size_t)g * 8;
    } else {
        size_t g2 = (size_t)(g - A_GROUPS);
        src = W + g2 * 8;
        dhi = g_whi + g2 * 8;
        dlo = g_wlo + g2 * 8;
    }
    float4 v0 = *(const float4*)src;
    float4 v1 = *(const float4*)(src + 4);
    float f[8] = {v0.x, v0.y, v0.z, v0.w, v1.x, v1.y, v1.z, v1.w};
    uint32_t hi[4], lo[4];
#pragma unroll
    for (int j = 0; j < 4; j++) {
        __nv_bfloat16 h0 = __float2bfloat16(f[2 * j]);
        __nv_bfloat16 h1 = __float2bfloat16(f[2 * j + 1]);
        __nv_bfloat16 l0 = __float2bfloat16(f[2 * j] - __bfloat162float(h0));
        __nv_bfloat16 l1 = __float2bfloat16(f[2 * j + 1] - __bfloat162float(h1));
        hi[j] = (uint32_t)__bfloat16_as_ushort(h0) | ((uint32_t)__bfloat16_as_ushort(h1) << 16);
        lo[j] = (uint32_t)__bfloat16_as_ushort(l0) | ((uint32_t)__bfloat16_as_ushort(l1) << 16);
    }
    *(uint4*)dhi = make_uint4(hi[0], hi[1], hi[2], hi[3]);
    *(uint4*)dlo = make_uint4(lo[0], lo[1], lo[2], lo[3]);
}

// ---------------- main GEMM kernel ----------------
__device__ __forceinline__ void load_stage(uint32_t S, int buf, int kt, int mb, int nb, int tid) {
    const uint32_t st = S + buf * STAGE;
    const int kbase = kt * BK;
    // A: 1024 16B-chunks each for hi/lo; thread -> 2 chunks
#pragma unroll
    for (int j = 0; j < 2; j++) {
        int q = tid * 2 + j;          // 0..1023
        int r = q >> 2, c = q & 3;    // r: 0..255 tile row, c: 16B chunk in k
        size_t so = (size_t)(mb * BM + r) * KK + kbase + c * 8;
        uint32_t d = st + swz(r, c);
        CP16(d, (const uint8_t*)(g_xhi + so));
        CP16(d + ST_ALO, (const uint8_t*)(g_xlo + so));
    }
    // B: 512 chunks each; thread -> 1 chunk
    {
        int r = tid >> 2, c = tid & 3;  // r: 0..127
        size_t so = (size_t)(nb * BN + r) * KK + kbase + c * 8;
        uint32_t d = st + ST_BHI + swz(r, c);
        CP16(d, (const uint8_t*)(g_whi + so));
        CP16(d + (ST_BLO - ST_BHI), (const uint8_t*)(g_wlo + so));
    }
    CP_COMMIT();
}

__global__ __launch_bounds__(THREADS, 1)
void gemm_mma_kernel(const float* __restrict__ bias, float* __restrict__ C) {
    extern __shared__ uint8_t smem[];
    const uint32_t S = smem_u32(smem);
    const int tid = threadIdx.x;
    const int l = tid & 31, wid = tid >> 5;
    const int mwarp = wid & 3;   // 4 M-warps of 64 rows
    const int nwarp = wid >> 2;  // 4 N-warps of 32 cols
    const int mb = blockIdx.x, nb = blockIdx.y;

    // lane components for ldmatrix addressing
    const int a_r = ((l >> 3) & 1) * 8 + (l & 7);  // row within 16-row A frag
    const int a_cs = (l >> 4) & 1;                 // k-chunk select
    const int b_n = ((l >> 4) & 1) * 8 + (l & 7);  // row (=n) within 16-row B pair
    const int b_cs = (l >> 3) & 1;

    float acc[4][4][4];
#pragma unroll
    for (int i = 0; i < 4; i++)
#pragma unroll
        for (int j = 0; j < 4; j++)
#pragma unroll
            for (int k = 0; k < 4; k++) acc[i][j][k] = 0.0f;

    load_stage(S, 0, 0, mb, nb, tid);
    load_stage(S, 1, 1, mb, nb, tid);

    for (int kt = 0; kt < NKT; kt++) {
        CP_WAIT1();
        __syncthreads();
        const uint32_t stg = S + (kt & 1) * STAGE;

#pragma unroll
        for (int ks = 0; ks < 2; ks++) {
            const int c0 = ks * 2;
            // B fragments: 2x ldmatrix.x4 (hi) + 2x (lo) -> 4 n8-frags each
            uint32_t Bh[8], Bl[8];
#pragma unroll
            for (int nf2 = 0; nf2 < 2; nf2++) {
                int r = nwarp * 32 + nf2 * 16 + b_n;
                uint32_t ad = stg + ST_BHI + swz(r, c0 + b_cs);
                ldm4(&Bh[nf2 * 4], ad);
                ldm4(&Bl[nf2 * 4], ad + (ST_BLO - ST_BHI));
            }
#pragma unroll
            for (int mf = 0; mf < 4; mf++) {
                int r = mwarp * 64 + mf * 16 + a_r;
                uint32_t ad = stg + swz(r, c0 + a_cs);
                uint32_t Ah[4], Al[4];
                ldm4(Ah, ad);
                ldm4(Al, ad + ST_ALO);
#pragma unroll
                for (int nf = 0; nf < 4; nf++) {
                    const uint32_t* bh = &Bh[(nf >> 1) * 4 + (nf & 1) * 2];
                    const uint32_t* bl = &Bl[(nf >> 1) * 4 + (nf & 1) * 2];
                    mma_bf16(acc[mf][nf], Ah, bh);
                    mma_bf16(acc[mf][nf], Ah, bl);
                    mma_bf16(acc[mf][nf], Al, bh);
                }
            }
        }
        __syncthreads();
        if (kt + 2 < NKT) load_stage(S, kt & 1, kt + 2, mb, nb, tid);
    }
    CP_WAIT0();

    // epilogue: bias + GELU, float2 stores
#pragma unroll
    for (int mf = 0; mf < 4; mf++) {
#pragma unroll
        for (int nf = 0; nf < 4; nf++) {
            int m0 = mb * BM + mwarp * 64 + mf * 16 + (l >> 2);
            int n0 = nb * BN + nwarp * 32 + nf * 8 + 2 * (l & 3);
            float b0 = __ldg(&bias[n0]);
            float b1 = __ldg(&bias[n0 + 1]);
            float2 v0, v1;
            v0.x = gelu_f(acc[mf][nf][0] + b0);
            v0.y = gelu_f(acc[mf][nf][1] + b1);
            v1.x = gelu_f(acc[mf][nf][2] + b0);
            v1.y = gelu_f(acc[mf][nf][3] + b1);
            *(float2*)&C[(size_t)m0 * OO + n0] = v0;
            *(float2*)&C[(size_t)(m0 + 8) * OO + n0] = v1;
        }
    }
}

// ---------------- launch ----------------
extern "C" void kernel_launch(void* const* d_in, const int* in_sizes, int n_in,
                              void* d_out, int out_size) {
    const float* x = (const float*)d_in[0];
    const float* W = (const float*)d_in[2];
    const float* b = (const float*)d_in[3];
    float* out = (float*)d_out;

    cudaFuncSetAttribute(gemm_mma_kernel,
                         cudaFuncAttributeMaxDynamicSharedMemorySize, SMEM_TOTAL);

    const int A_GROUPS = NN * (KK / 8);
    const int B_GROUPS = OO * (KK / 8);
    pack_kernel<<<(A_GROUPS + B_GROUPS) / 256, 256>>>(x, W);

    dim3 grid(NN / BM, OO / BN);  // (32, 4) = 128 CTAs, single wave
    gemm_mma_kernel<<<grid, THREADS, SMEM_TOTAL>>>(b, out);
}

// round 5
// speedup vs baseline: 1.9331x; 1.0438x over previous
#include <cuda_runtime.h>
#include <cuda_bf16.h>
#include <cstdint>
#include <math.h>

// out = GELU_exact(x @ W.T + b)
// Split-precision bf16 mma.sync GEMM: acc += Ahi*Bhi + Ahi*Blo + Alo*Bhi (fp32 accum).
// R5: 256 CTAs (all SMs, 2/SM), term-major MMA ordering (breaks RAW chains),
// 3-stage cp.async pipeline.

#define NN 8192
#define KK 512
#define OO 512

#define BM 128
#define BN 128
#define BK 32
#define NKT (KK / BK)          // 16
#define THREADS 256

// stage layout (bytes): Ahi[128x32] 8K | Alo 8K | Bhi[128x32] 8K | Blo 8K
#define ST_ALO  8192
#define ST_BHI  16384
#define ST_BLO  24576
#define STAGE   32768
#define NSTAGE  3
#define SMEM_TOTAL (NSTAGE * STAGE)   // 96 KB

__device__ __align__(128) __nv_bfloat16 g_xhi[NN * KK];
__device__ __align__(128) __nv_bfloat16 g_xlo[NN * KK];
__device__ __align__(128) __nv_bfloat16 g_whi[OO * KK];
__device__ __align__(128) __nv_bfloat16 g_wlo[OO * KK];

__device__ __forceinline__ uint32_t smem_u32(const void* p) {
    uint32_t a;
    asm("{ .reg .u64 t; cvta.to.shared.u64 t, %1; cvt.u32.u64 %0, t; }" : "=r"(a) : "l"(p));
    return a;
}

#define CP16(dst, src) \
    asm volatile("cp.async.cg.shared.global [%0], [%1], 16;" :: "r"(dst), "l"(src) : "memory")
#define CP_COMMIT() asm volatile("cp.async.commit_group;" ::: "memory")
#define CP_WAIT1()  asm volatile("cp.async.wait_group 1;" ::: "memory")

__device__ __forceinline__ void ldm4(uint32_t* r, uint32_t addr) {
    asm volatile("ldmatrix.sync.aligned.m8n8.x4.shared.b16 {%0,%1,%2,%3}, [%4];"
                 : "=r"(r[0]), "=r"(r[1]), "=r"(r[2]), "=r"(r[3]) : "r"(addr));
}

__device__ __forceinline__ void mma_bf16(float* d, const uint32_t* a, const uint32_t* b) {
    asm volatile(
        "mma.sync.aligned.m16n8k16.row.col.f32.bf16.bf16.f32 "
        "{%0,%1,%2,%3}, {%4,%5,%6,%7}, {%8,%9}, {%0,%1,%2,%3};"
        : "+f"(d[0]), "+f"(d[1]), "+f"(d[2]), "+f"(d[3])
        : "r"(a[0]), "r"(a[1]), "r"(a[2]), "r"(a[3]), "r"(b[0]), "r"(b[1]));
}

// swizzled byte offset inside a tile: row r (64B rows = 4 x 16B chunks), chunk c
__device__ __forceinline__ uint32_t swz(int r, int c) {
    return (uint32_t)(r * 64 + ((c ^ ((r >> 1) & 3)) << 4));
}

// A&S 7.1.26 erf (abs err 1.5e-7)
__device__ __forceinline__ float gelu_f(float h) {
    float s = h * 0.70710678118654752f;
    float a = fabsf(s);
    float t = __frcp_rn(fmaf(0.3275911f, a, 1.0f));
    float p = fmaf(fmaf(fmaf(fmaf(1.061405429f, t, -1.453152027f), t, 1.421413741f),
                        t, -0.284496736f), t, 0.254829592f) * t;
    float e = __expf(-a * a);
    float erfv = fmaf(-p, e, 1.0f);
    erfv = copysignf(erfv, s);
    return 0.5f * h * (1.0f + erfv);
}

// ---------------- pack kernel: f32 -> bf16 hi/lo ----------------
__global__ __launch_bounds__(256) void pack_kernel(const float* __restrict__ x,
                                                   const float* __restrict__ W) {
    const int g = blockIdx.x * 256 + threadIdx.x;
    const int A_GROUPS = NN * (KK / 8);   // 524288
    const float* src;
    __nv_bfloat16 *dhi, *dlo;
    if (g < A_GROUPS) {
        src = x + (size_t)g * 8;
        dhi = g_xhi + (size_t)g * 8;
        dlo = g_xlo + (size_t)g * 8;
    } else {
        size_t g2 = (size_t)(g - A_GROUPS);
        src = W + g2 * 8;
        dhi = g_whi + g2 * 8;
        dlo = g_wlo + g2 * 8;
    }
    float4 v0 = *(const float4*)src;
    float4 v1 = *(const float4*)(src + 4);
    float f[8] = {v0.x, v0.y, v0.z, v0.w, v1.x, v1.y, v1.z, v1.w};
    uint32_t hi[4], lo[4];
#pragma unroll
    for (int j = 0; j < 4; j++) {
        __nv_bfloat16 h0 = __float2bfloat16(f[2 * j]);
        __nv_bfloat16 h1 = __float2bfloat16(f[2 * j + 1]);
        __nv_bfloat16 l0 = __float2bfloat16(f[2 * j] - __bfloat162float(h0));
        __nv_bfloat16 l1 = __float2bfloat16(f[2 * j + 1] - __bfloat162float(h1));
        hi[j] = (uint32_t)__bfloat16_as_ushort(h0) | ((uint32_t)__bfloat16_as_ushort(h1) << 16);
        lo[j] = (uint32_t)__bfloat16_as_ushort(l0) | ((uint32_t)__bfloat16_as_ushort(l1) << 16);
    }
    *(uint4*)dhi = make_uint4(hi[0], hi[1], hi[2], hi[3]);
    *(uint4*)dlo = make_uint4(lo[0], lo[1], lo[2], lo[3]);
}

// ---------------- main GEMM kernel ----------------
__device__ __forceinline__ void load_stage(uint32_t S, int buf, int kt, int mb, int nb, int tid) {
    const uint32_t st = S + buf * STAGE;
    const int kbase = kt * BK;
    // A: 512 chunk positions (128 rows x 4 chunks); thread -> 2 positions, hi+lo
#pragma unroll
    for (int j = 0; j < 2; j++) {
        int q = tid + j * 256;        // 0..511
        int r = q >> 2, c = q & 3;
        size_t so = (size_t)(mb * BM + r) * KK + kbase + c * 8;
        uint32_t d = st + swz(r, c);
        CP16(d, (const uint8_t*)(g_xhi + so));
        CP16(d + ST_ALO, (const uint8_t*)(g_xlo + so));
    }
    // B: same shape
#pragma unroll
    for (int j = 0; j < 2; j++) {
        int q = tid + j * 256;
        int r = q >> 2, c = q & 3;
        size_t so = (size_t)(nb * BN + r) * KK + kbase + c * 8;
        uint32_t d = st + ST_BHI + swz(r, c);
        CP16(d, (const uint8_t*)(g_whi + so));
        CP16(d + (ST_BLO - ST_BHI), (const uint8_t*)(g_wlo + so));
    }
    CP_COMMIT();
}

__global__ __launch_bounds__(THREADS, 2)
void gemm_mma_kernel(const float* __restrict__ bias, float* __restrict__ C) {
    extern __shared__ uint8_t smem[];
    const uint32_t S = smem_u32(smem);
    const int tid = threadIdx.x;
    const int l = tid & 31, wid = tid >> 5;
    const int mwarp = wid & 1;   // 2 M-warps of 64 rows
    const int nwarp = wid >> 1;  // 4 N-warps of 32 cols
    const int mb = blockIdx.x, nb = blockIdx.y;

    const int a_r = ((l >> 3) & 1) * 8 + (l & 7);
    const int a_cs = (l >> 4) & 1;
    const int b_n = ((l >> 4) & 1) * 8 + (l & 7);
    const int b_cs = (l >> 3) & 1;

    float acc[4][4][4];
#pragma unroll
    for (int i = 0; i < 4; i++)
#pragma unroll
        for (int j = 0; j < 4; j++)
#pragma unroll
            for (int k = 0; k < 4; k++) acc[i][j][k] = 0.0f;

    load_stage(S, 0, 0, mb, nb, tid);
    load_stage(S, 1, 1, mb, nb, tid);

    for (int kt = 0; kt < NKT; kt++) {
        CP_WAIT1();
        __syncthreads();
        if (kt + 2 < NKT) load_stage(S, (kt + 2) % NSTAGE, kt + 2, mb, nb, tid);
        const uint32_t stg = S + (kt % NSTAGE) * STAGE;

#pragma unroll
        for (int ks = 0; ks < 2; ks++) {
            const int c0 = ks * 2;
            uint32_t Bh[8], Bl[8];
#pragma unroll
            for (int nf2 = 0; nf2 < 2; nf2++) {
                int r = nwarp * 32 + nf2 * 16 + b_n;
                uint32_t ad = stg + ST_BHI + swz(r, c0 + b_cs);
                ldm4(&Bh[nf2 * 4], ad);
                ldm4(&Bl[nf2 * 4], ad + (ST_BLO - ST_BHI));
            }
            uint32_t Ah[4][4];
#pragma unroll
            for (int mf = 0; mf < 4; mf++) {
                int r = mwarp * 64 + mf * 16 + a_r;
                ldm4(Ah[mf], stg + swz(r, c0 + a_cs));
            }
            // term hh: 16 independent accumulator chains
#pragma unroll
            for (int mf = 0; mf < 4; mf++)
#pragma unroll
                for (int nf = 0; nf < 4; nf++)
                    mma_bf16(acc[mf][nf], Ah[mf], &Bh[(nf >> 1) * 4 + (nf & 1) * 2]);
            // term hl
#pragma unroll
            for (int mf = 0; mf < 4; mf++)
#pragma unroll
                for (int nf = 0; nf < 4; nf++)
                    mma_bf16(acc[mf][nf], Ah[mf], &Bl[(nf >> 1) * 4 + (nf & 1) * 2]);
            // term lh (Ah dead; load Al)
            uint32_t Al[4][4];
#pragma unroll
            for (int mf = 0; mf < 4; mf++) {
                int r = mwarp * 64 + mf * 16 + a_r;
                ldm4(Al[mf], stg + ST_ALO + swz(r, c0 + a_cs));
            }
#pragma unroll
            for (int mf = 0; mf < 4; mf++)
#pragma unroll
                for (int nf = 0; nf < 4; nf++)
                    mma_bf16(acc[mf][nf], Al[mf], &Bh[(nf >> 1) * 4 + (nf & 1) * 2]);
        }
        __syncthreads();
    }

    // epilogue: bias + GELU
#pragma unroll
    for (int mf = 0; mf < 4; mf++) {
#pragma unroll
        for (int nf = 0; nf < 4; nf++) {
            int m0 = mb * BM + mwarp * 64 + mf * 16 + (l >> 2);
            int n0 = nb * BN + nwarp * 32 + nf * 8 + 2 * (l & 3);
            float b0 = __ldg(&bias[n0]);
            float b1 = __ldg(&bias[n0 + 1]);
            float2 v0, v1;
            v0.x = gelu_f(acc[mf][nf][0] + b0);
            v0.y = gelu_f(acc[mf][nf][1] + b1);
            v1.x = gelu_f(acc[mf][nf][2] + b0);
            v1.y = gelu_f(acc[mf][nf][3] + b1);
            *(float2*)&C[(size_t)m0 * OO + n0] = v0;
            *(float2*)&C[(size_t)(m0 + 8) * OO + n0] = v1;
        }
    }
}

// ---------------- launch ----------------
extern "C" void kernel_launch(void* const* d_in, const int* in_sizes, int n_in,
                              void* d_out, int out_size) {
    const float* x = (const float*)d_in[0];
    const float* W = (const float*)d_in[2];
    const float* b = (const float*)d_in[3];
    float* out = (float*)d_out;

    cudaFuncSetAttribute(gemm_mma_kernel,
                         cudaFuncAttributeMaxDynamicSharedMemorySize, SMEM_TOTAL);

    const int A_GROUPS = NN * (KK / 8);
    const int B_GROUPS = OO * (KK / 8);
    pack_kernel<<<(A_GROUPS + B_GROUPS) / 256, 256>>>(x, W);

    dim3 grid(NN / BM, OO / BN);  // (64, 4) = 256 CTAs, 2/SM
    gemm_mma_kernel<<<grid, THREADS, SMEM_TOTAL>>>(b, out);
}

// round 6
// speedup vs baseline: 1.9814x; 1.0250x over previous
#include <cuda_runtime.h>
#include <cuda_bf16.h>
#include <cstdint>
#include <math.h>

// out = GELU_exact(x @ W.T + b)
// Split-precision bf16 mma.sync GEMM: acc += Ahi*Bhi + Ahi*Blo + Alo*Bhi (fp32 accum).
// R6: 512-thread CTAs, warp tile 32x32 (acc=32 regs), launch_bounds(512,2)
// -> 8 warps/SMSP for latency hiding; term-streamed frags to fit 64-reg cap;
// one barrier per k-tile (3-stage pipeline makes the second barrier redundant).

#define NN 8192
#define KK 512
#define OO 512

#define BM 128
#define BN 128
#define BK 32
#define NKT (KK / BK)          // 16
#define THREADS 512

// stage layout (bytes): Ahi[128x32] 8K | Alo 8K | Bhi 8K | Blo 8K
#define ST_ALO  8192
#define ST_BHI  16384
#define ST_BLO  24576
#define STAGE   32768
#define NSTAGE  3
#define SMEM_TOTAL (NSTAGE * STAGE)   // 96 KB

// unified packed scratch: [xhi | xlo | whi | wlo]
#define OFF_XHI 0
#define OFF_XLO (NN * KK)
#define OFF_WHI (2 * NN * KK)
#define OFF_WLO (2 * NN * KK + OO * KK)
__device__ __align__(128) __nv_bfloat16 g_pack[2 * NN * KK + 2 * OO * KK];

__device__ __forceinline__ uint32_t smem_u32(const void* p) {
    uint32_t a;
    asm("{ .reg .u64 t; cvta.to.shared.u64 t, %1; cvt.u32.u64 %0, t; }" : "=r"(a) : "l"(p));
    return a;
}

#define CP16(dst, src) \
    asm volatile("cp.async.cg.shared.global [%0], [%1], 16;" :: "r"(dst), "l"(src) : "memory")
#define CP_COMMIT() asm volatile("cp.async.commit_group;" ::: "memory")
#define CP_WAIT1()  asm volatile("cp.async.wait_group 1;" ::: "memory")

__device__ __forceinline__ void ldm4(uint32_t* r, uint32_t addr) {
    asm volatile("ldmatrix.sync.aligned.m8n8.x4.shared.b16 {%0,%1,%2,%3}, [%4];"
                 : "=r"(r[0]), "=r"(r[1]), "=r"(r[2]), "=r"(r[3]) : "r"(addr));
}

__device__ __forceinline__ void mma_bf16(float* d, const uint32_t* a, const uint32_t* b) {
    asm volatile(
        "mma.sync.aligned.m16n8k16.row.col.f32.bf16.bf16.f32 "
        "{%0,%1,%2,%3}, {%4,%5,%6,%7}, {%8,%9}, {%0,%1,%2,%3};"
        : "+f"(d[0]), "+f"(d[1]), "+f"(d[2]), "+f"(d[3])
        : "r"(a[0]), "r"(a[1]), "r"(a[2]), "r"(a[3]), "r"(b[0]), "r"(b[1]));
}

// swizzled byte offset inside a tile: row r (64B rows = 4 x 16B chunks), chunk c
__device__ __forceinline__ uint32_t swz(int r, int c) {
    return (uint32_t)(r * 64 + ((c ^ ((r >> 1) & 3)) << 4));
}

// A&S 7.1.26 erf (abs err 1.5e-7)
__device__ __forceinline__ float gelu_f(float h) {
    float s = h * 0.70710678118654752f;
    float a = fabsf(s);
    float t = __frcp_rn(fmaf(0.3275911f, a, 1.0f));
    float p = fmaf(fmaf(fmaf(fmaf(1.061405429f, t, -1.453152027f), t, 1.421413741f),
                        t, -0.284496736f), t, 0.254829592f) * t;
    float e = __expf(-a * a);
    float erfv = fmaf(-p, e, 1.0f);
    erfv = copysignf(erfv, s);
    return 0.5f * h * (1.0f + erfv);
}

// ---------------- pack kernel: f32 -> bf16 hi/lo ----------------
__global__ __launch_bounds__(256) void pack_kernel(const float* __restrict__ x,
                                                   const float* __restrict__ W) {
    const int g = blockIdx.x * 256 + threadIdx.x;
    const int A_GROUPS = NN * (KK / 8);   // 524288
    const float* src;
    __nv_bfloat16 *dhi, *dlo;
    if (g < A_GROUPS) {
        src = x + (size_t)g * 8;
        dhi = g_pack + OFF_XHI + (size_t)g * 8;
        dlo = g_pack + OFF_XLO + (size_t)g * 8;
    } else {
        size_t g2 = (size_t)(g - A_GROUPS);
        src = W + g2 * 8;
        dhi = g_pack + OFF_WHI + g2 * 8;
        dlo = g_pack + OFF_WLO + g2 * 8;
    }
    float4 v0 = *(const float4*)src;
    float4 v1 = *(const float4*)(src + 4);
    float f[8] = {v0.x, v0.y, v0.z, v0.w, v1.x, v1.y, v1.z, v1.w};
    uint32_t hi[4], lo[4];
#pragma unroll
    for (int j = 0; j < 4; j++) {
        __nv_bfloat16 h0 = __float2bfloat16(f[2 * j]);
        __nv_bfloat16 h1 = __float2bfloat16(f[2 * j + 1]);
        __nv_bfloat16 l0 = __float2bfloat16(f[2 * j] - __bfloat162float(h0));
        __nv_bfloat16 l1 = __float2bfloat16(f[2 * j + 1] - __bfloat162float(h1));
        hi[j] = (uint32_t)__bfloat16_as_ushort(h0) | ((uint32_t)__bfloat16_as_ushort(h1) << 16);
        lo[j] = (uint32_t)__bfloat16_as_ushort(l0) | ((uint32_t)__bfloat16_as_ushort(l1) << 16);
    }
    *(uint4*)dhi = make_uint4(hi[0], hi[1], hi[2], hi[3]);
    *(uint4*)dlo = make_uint4(lo[0], lo[1], lo[2], lo[3]);
}

// ---------------- main GEMM kernel ----------------
__device__ __forceinline__ void load_stage(uint32_t S, int buf, int kt, int mb, int nb, int tid) {
    const uint32_t st = S + buf * STAGE;
    const int kbase = kt * BK;
    const int r = tid >> 2, c = tid & 3;   // 128 rows x 4 chunks, one position/thread
    const uint32_t sw = swz(r, c);
    {   // A hi + lo
        size_t so = (size_t)(mb * BM + r) * KK + kbase + c * 8;
        CP16(st + sw, (const uint8_t*)(g_pack + OFF_XHI + so));
        CP16(st + ST_ALO + sw, (const uint8_t*)(g_pack + OFF_XLO + so));
    }
    {   // B hi + lo
        size_t so = (size_t)(nb * BN + r) * KK + kbase + c * 8;
        CP16(st + ST_BHI + sw, (const uint8_t*)(g_pack + OFF_WHI + so));
        CP16(st + ST_BLO + sw, (const uint8_t*)(g_pack + OFF_WLO + so));
    }
    CP_COMMIT();
}

__global__ __launch_bounds__(THREADS, 2)
void gemm_mma_kernel(const float* __restrict__ bias, float* __restrict__ C) {
    extern __shared__ uint8_t smem[];
    const uint32_t S = smem_u32(smem);
    const int tid = threadIdx.x;
    const int l = tid & 31, wid = tid >> 5;
    const int mwarp = wid & 3;   // 4 M-warps of 32 rows
    const int nwarp = wid >> 2;  // 4 N-warps of 32 cols
    const int mb = blockIdx.x, nb = blockIdx.y;

    const int a_r = ((l >> 3) & 1) * 8 + (l & 7);
    const int a_cs = (l >> 4) & 1;
    const int b_n = ((l >> 4) & 1) * 8 + (l & 7);
    const int b_cs = (l >> 3) & 1;

    float acc[2][4][4];
#pragma unroll
    for (int i = 0; i < 2; i++)
#pragma unroll
        for (int j = 0; j < 4; j++)
#pragma unroll
            for (int k = 0; k < 4; k++) acc[i][j][k] = 0.0f;

    load_stage(S, 0, 0, mb, nb, tid);
    load_stage(S, 1, 1, mb, nb, tid);

    for (int kt = 0; kt < NKT; kt++) {
        CP_WAIT1();
        __syncthreads();
        if (kt + 2 < NKT) load_stage(S, (kt + 2) % NSTAGE, kt + 2, mb, nb, tid);
        const uint32_t stg = S + (kt % NSTAGE) * STAGE;

#pragma unroll
        for (int ks = 0; ks < 2; ks++) {
            const int c0 = ks * 2;
            uint32_t Bh[8], Ah[8], T[8];
            // B hi (4 n8-frags), A hi (2 m16-frags)
#pragma unroll
            for (int nf2 = 0; nf2 < 2; nf2++)
                ldm4(&Bh[nf2 * 4], stg + ST_BHI + swz(nwarp * 32 + nf2 * 16 + b_n, c0 + b_cs));
#pragma unroll
            for (int mf = 0; mf < 2; mf++)
                ldm4(&Ah[mf * 4], stg + swz(mwarp * 32 + mf * 16 + a_r, c0 + a_cs));
            // hh
#pragma unroll
            for (int mf = 0; mf < 2; mf++)
#pragma unroll
                for (int nf = 0; nf < 4; nf++)
                    mma_bf16(acc[mf][nf], &Ah[mf * 4], &Bh[nf * 2]);
            // T = A lo ; lh
#pragma unroll
            for (int mf = 0; mf < 2; mf++)
                ldm4(&T[mf * 4], stg + ST_ALO + swz(mwarp * 32 + mf * 16 + a_r, c0 + a_cs));
#pragma unroll
            for (int mf = 0; mf < 2; mf++)
#pragma unroll
                for (int nf = 0; nf < 4; nf++)
                    mma_bf16(acc[mf][nf], &T[mf * 4], &Bh[nf * 2]);
            // T = B lo ; hl
#pragma unroll
            for (int nf2 = 0; nf2 < 2; nf2++)
                ldm4(&T[nf2 * 4], stg + ST_BLO + swz(nwarp * 32 + nf2 * 16 + b_n, c0 + b_cs));
#pragma unroll
            for (int mf = 0; mf < 2; mf++)
#pragma unroll
                for (int nf = 0; nf < 4; nf++)
                    mma_bf16(acc[mf][nf], &Ah[mf * 4], &T[nf * 2]);
        }
    }

    // epilogue: bias + GELU
#pragma unroll
    for (int mf = 0; mf < 2; mf++) {
#pragma unroll
        for (int nf = 0; nf < 4; nf++) {
            int m0 = mb * BM + mwarp * 32 + mf * 16 + (l >> 2);
            int n0 = nb * BN + nwarp * 32 + nf * 8 + 2 * (l & 3);
            float b0 = __ldg(&bias[n0]);
            float b1 = __ldg(&bias[n0 + 1]);
            float2 v0, v1;
            v0.x = gelu_f(acc[mf][nf][0] + b0);
            v0.y = gelu_f(acc[mf][nf][1] + b1);
            v1.x = gelu_f(acc[mf][nf][2] + b0);
            v1.y = gelu_f(acc[mf][nf][3] + b1);
            *(float2*)&C[(size_t)m0 * OO + n0] = v0;
            *(float2*)&C[(size_t)(m0 + 8) * OO + n0] = v1;
        }
    }
}

// ---------------- launch ----------------
extern "C" void kernel_launch(void* const* d_in, const int* in_sizes, int n_in,
                              void* d_out, int out_size) {
    const float* x = (const float*)d_in[0];
    const float* W = (const float*)d_in[2];
    const float* b = (const float*)d_in[3];
    float* out = (float*)d_out;

    cudaFuncSetAttribute(gemm_mma_kernel,
                         cudaFuncAttributeMaxDynamicSharedMemorySize, SMEM_TOTAL);

    const int A_GROUPS = NN * (KK / 8);
    const int B_GROUPS = OO * (KK / 8);
    pack_kernel<<<(A_GROUPS + B_GROUPS) / 256, 256>>>(x, W);

    dim3 grid(NN / BM, OO / BN);  // (64, 4) = 256 CTAs, 2/SM, single wave
    gemm_mma_kernel<<<grid, THREADS, SMEM_TOTAL>>>(b, out);
}